// round 14
// baseline (speedup 1.0000x reference)
#include <cuda_runtime.h>
#include <cuda_fp16.h>
#include <cstdint>

#define F0C 39
#define DD 32
#define SS 200
#define NFH 100

#define NFP0 40                 // padded n-run, layer 0
#define NFP12 104               // padded n-run, layers 1,2
#define T2_0 49                 // k32 tiles (Kp0=1568)
#define T2_12 127               // k32 tiles (Kp12=4064)
#define T16_0 98
#define T16_12 254

#define NBATCH 4
#define NT 256                  // 8 warps, 2 CTAs/SM

#define BBLK16 6400             // 25 n8-tiles x 2 k8 x 128B
#define BBLK32 12800
#define ABUF16 4096             // 128 rows x k16 x 2B
#define ABUF32 8192
#define IMG0_BYTES (T16_0 * BBLK16)
#define IMG12_BYTES (T16_12 * BBLK16)

#define SM_BIAS 0               // 2400 -> 2432
#define SM_XH   2432            // 9984 -> 12416
#define SM_HT0  12416           // 10240 -> 22656
#define SM_HT   22656           // 26624 -> 49280
#define SM_LUT  49280           // 2032 -> 51328
#define SM_A    51328           // 2*8192 -> 67712
#define SM_B    67712           // 3*12800 -> 106112
#define SMEM_TOTAL 106112

__device__ __align__(16) unsigned char g_wimg[IMG0_BYTES + 2 * IMG12_BYTES];

__device__ __forceinline__ void cp_async16(uint32_t s, const void* g) {
    asm volatile("cp.async.cg.shared.global [%0], [%1], 16;\n" :: "r"(s), "l"(g) : "memory");
}
__device__ __forceinline__ void cp_commit() { asm volatile("cp.async.commit_group;\n" ::: "memory"); }
template <int N> __device__ __forceinline__ void cp_wait() {
    asm volatile("cp.async.wait_group %0;\n" :: "n"(N) : "memory");
}
__device__ __forceinline__ uint32_t cvth2(float p0, float p1) {
    uint32_t r;
    asm("cvt.rn.f16x2.f32 %0, %1, %2;" : "=r"(r) : "f"(p1), "f"(p0));
    return r;
}
__device__ __forceinline__ void ldsm4(uint32_t* r, uint32_t a) {
    asm volatile("ldmatrix.sync.aligned.m8n8.x4.shared.b16 {%0,%1,%2,%3}, [%4];"
                 : "=r"(r[0]), "=r"(r[1]), "=r"(r[2]), "=r"(r[3]) : "r"(a));
}
__device__ __forceinline__ void ldsm2(uint32_t* r, uint32_t a) {
    asm volatile("ldmatrix.sync.aligned.m8n8.x2.shared.b16 {%0,%1}, [%2];"
                 : "=r"(r[0]), "=r"(r[1]) : "r"(a));
}
#define MMA(D, A, B0, B1)                                                     \
    asm volatile("mma.sync.aligned.m16n8k16.row.col.f32.f16.f16.f32 "         \
                 "{%0,%1,%2,%3}, {%4,%5,%6,%7}, {%8,%9}, {%0,%1,%2,%3};"      \
                 : "+f"(D[0]), "+f"(D[1]), "+f"(D[2]), "+f"(D[3])             \
                 : "r"((A)[0]), "r"((A)[1]), "r"((A)[2]), "r"((A)[3]),        \
                   "r"(B0), "r"(B1))

// ---- prep: W -> padded-K tile-packed fp16 images (25 n8-tiles, no n-pad) ----
__global__ void prep_kernel(const float* __restrict__ W, int NF, int NFP,
                            int T16, int which)
{
    unsigned char* img = g_wimg +
        ((which == 0) ? 0 : (which == 1) ? IMG0_BYTES : (IMG0_BYTES + IMG12_BYTES));
    int idx = blockIdx.x * 256 + threadIdx.x;
    if (idx >= T16 * 8 * SS) return;
    int o = idx % SS;
    int r = idx / SS;
    int p = r & 7, t = r >> 3;
    int c0 = t * 16 + 2 * p;
    float v[2];
#pragma unroll
    for (int u = 0; u < 2; u++) {
        int c = c0 + u;
        int m = c / NFP, j = c - m * NFP;
        v[u] = (m < F0C && j < NF) ? W[(size_t)(m * NF + j) * SS + o] : 0.f;
    }
    uint32_t hp = cvth2(v[0], v[1]);
    int nt = o >> 3, nr = o & 7, ks = p >> 2, jj = p & 3;
    size_t off = (size_t)t * BBLK16 + (nt * 2 + ks) * 128 + nr * 16 + jj * 4;
    *(uint32_t*)(img + off) = hp;
}

// ---- main ----
__device__ __forceinline__ void prefetchB(const unsigned char* img, int t, int T2,
                                          uint32_t sb, int tid)
{
    if (t < T2) {
        const unsigned char* src = img + (size_t)t * BBLK32;
        uint32_t dst = sb + SM_B + (uint32_t)(t % 3) * (uint32_t)BBLK32;
        for (int i = tid; i < BBLK32 / 16; i += NT)
            cp_async16(dst + 16u * (uint32_t)i, src + 16 * i);
    }
    cp_commit();
}

// A products for one k32 block: thread (rA = tid&127, sA = tid>>7): 2 octets.
template <int NFP>
__device__ __forceinline__ void stageA(int t, const uint32_t* lut,
                                       const __half* xrow, const __half* hrow,
                                       char* abuf, int rA, int sA)
{
    uint32_t base = (uint32_t)(sA * ABUF16 + (rA >> 3) * 256 + (rA & 7) * 16);
#pragma unroll
    for (int kh = 0; kh < 2; kh++) {
        uint32_t L = lut[t * 4 + sA * 2 + kh];
        uint4 hv = *(const uint4*)(hrow + (L & 0xffffu));
        __half2 xx = __half2half2(xrow[L >> 16]);
        const __half2* h2 = (const __half2*)&hv;
        uint4 ov;
        ((__half2*)&ov)[0] = __hmul2(xx, h2[0]);
        ((__half2*)&ov)[1] = __hmul2(xx, h2[1]);
        ((__half2*)&ov)[2] = __hmul2(xx, h2[2]);
        ((__half2*)&ov)[3] = __hmul2(xx, h2[3]);
        *(uint4*)(abuf + base + (uint32_t)kh * 128u) = ov;
    }
}

template <int NFP, int LMODE>
__device__ void run_layer(const unsigned char* img, int T2,
                          const __half* xsh, const __half* hsrc, __half* hT,
                          const float* bias, float* out,
                          char* smem, uint32_t sb, int bbase, int Btot)
{
    const int tid = threadIdx.x;
    const int w = tid >> 5, lane = tid & 31;
    const int mq = w >> 1, nh = w & 1;       // mq 0..3 (batch), nh 0..1

    const int sA = tid >> 7;
    const int rA = tid & 127;
    const int blA = rA >> 5, dA = rA & 31;
    const __half* xrow = xsh + blA * (F0C * DD) + dA;
    const __half* hrow = hsrc + (blA * DD + dA) * NFP;

    // octet LUT (clamped past valid range; W image zero there)
    uint32_t* lut = (uint32_t*)(smem + SM_LUT);
    for (int o8 = tid; o8 < T2 * 4; o8 += NT) {
        int c0 = o8 * 8;
        int m = c0 / NFP, j0 = c0 - m * NFP;
        if (m >= F0C) { m = 0; j0 = 0; }
        lut[o8] = ((uint32_t)(m * DD) << 16) | (uint32_t)j0;
    }

    float acc[2][13][4];
#pragma unroll
    for (int mt = 0; mt < 2; mt++)
#pragma unroll
        for (int nt = 0; nt < 13; nt++)
#pragma unroll
            for (int q = 0; q < 4; q++) acc[mt][nt][q] = 0.f;

    prefetchB(img, 0, T2, sb, tid);
    prefetchB(img, 1, T2, sb, tid);
    __syncthreads();                    // lut + hsrc visible
    stageA<NFP>(0, lut, xrow, hrow, smem + SM_A, rA, sA);

    const uint32_t aoff = ((lane >> 3) & 1) * 256u + (lane >> 4) * 128u + (lane & 7) * 16u;
    const uint32_t boff = (uint32_t)lane * 16u;
    const uint32_t boff2 = (uint32_t)(lane & 15) * 16u;

    for (int t = 0; t < T2; t++) {
        __syncthreads();   // closes body t-1: A(t) visible, B slot (t+2)%3 free

        if (t + 1 < T2)
            stageA<NFP>(t + 1, lut, xrow, hrow,
                        smem + SM_A + ((t + 1) & 1) * ABUF32, rA, sA);
        prefetchB(img, t + 2, T2, sb, tid);
        cp_wait<2>();      // block t landed; t+1, t+2 in flight

        uint32_t ab = sb + SM_A + (uint32_t)(t & 1) * ABUF32 + (uint32_t)mq * 1024u;
        // nh=0: tiles 0..12 (ldsm2 tail); nh=1: tiles 13..24 (no tail)
        uint32_t bbase2 = sb + SM_B + (uint32_t)(t % 3) * (uint32_t)BBLK32 + (uint32_t)nh * 3328u;
#pragma unroll
        for (int s = 0; s < 2; s++) {
            uint32_t ah[2][4];
            ldsm4(ah[0], ab + (uint32_t)s * (uint32_t)ABUF16 + aoff);
            ldsm4(ah[1], ab + (uint32_t)s * (uint32_t)ABUF16 + 512u + aoff);
            uint32_t bb = bbase2 + (uint32_t)s * (uint32_t)BBLK16;
#pragma unroll
            for (int i = 0; i < 6; i++) {
                uint32_t bh[4];
                ldsm4(bh, bb + i * 512u + boff);
                MMA(acc[0][2 * i], ah[0], bh[0], bh[1]);
                MMA(acc[1][2 * i], ah[1], bh[0], bh[1]);
                MMA(acc[0][2 * i + 1], ah[0], bh[2], bh[3]);
                MMA(acc[1][2 * i + 1], ah[1], bh[2], bh[3]);
            }
            if (nh == 0) {            // warp-uniform
                uint32_t bh2[2];
                ldsm2(bh2, bb + 3072u + boff2);
                MMA(acc[0][12], ah[0], bh2[0], bh2[1]);
                MMA(acc[1][12], ah[1], bh2[0], bh2[1]);
            }
        }
    }
    cp_wait<0>();

    // ---- epilogue: warp (mq,nh) owns batch mq fully in d ----
    int b = bbase + mq;
    bool bok = b < Btot;
    int quad = lane & 3, ldq = lane >> 2;
    const float* bi = bias + LMODE * SS;
    float* outp = out + (size_t)b * (2 * SS);
    __half* hTw = hT + (size_t)(mq * DD) * NFP12;
    const int ntl = 13 - nh;          // 13 or 12, warp-uniform
#pragma unroll
    for (int nt = 0; nt < 13; nt++) {
        if (nt >= ntl) break;
        int oe = nh * 104 + nt * 8 + 2 * quad;
        float be = bi[oe], bo = bi[oe + 1];
        float se = 0.f, so = 0.f;
#pragma unroll
        for (int mt = 0; mt < 2; mt++) {
            float v0 = fmaxf(acc[mt][nt][0] + be, 0.f);
            float v1 = fmaxf(acc[mt][nt][1] + bo, 0.f);
            float v2 = fmaxf(acc[mt][nt][2] + be, 0.f);
            float v3 = fmaxf(acc[mt][nt][3] + bo, 0.f);
            if (LMODE < 2 && bok) {
                int d0 = mt * 16 + ldq;
                if (oe < NFH) {
                    hTw[d0 * NFP12 + oe] = __float2half(v0);
                    hTw[(d0 + 8) * NFP12 + oe] = __float2half(v2);
                }
                if (oe + 1 < NFH) {
                    hTw[d0 * NFP12 + oe + 1] = __float2half(v1);
                    hTw[(d0 + 8) * NFP12 + oe + 1] = __float2half(v3);
                }
            }
            se += v0 + v2;
            so += v1 + v3;
        }
        se += __shfl_xor_sync(0xffffffffu, se, 4);
        se += __shfl_xor_sync(0xffffffffu, se, 8);
        se += __shfl_xor_sync(0xffffffffu, se, 16);
        so += __shfl_xor_sync(0xffffffffu, so, 4);
        so += __shfl_xor_sync(0xffffffffu, so, 8);
        so += __shfl_xor_sync(0xffffffffu, so, 16);
        if (ldq == 0 && bok) {
            bool de = (LMODE == 2) ? (oe < SS) : (oe >= NFH && oe < SS);
            bool dd = (LMODE == 2) ? (oe + 1 < SS) : (oe + 1 >= NFH && oe + 1 < SS);
            int che = (LMODE == 0) ? (oe - NFH) : (LMODE == 1) ? oe : (SS + oe);
            if (de) outp[che] = se;
            if (dd) outp[che + 1] = so;
        }
    }
    __syncthreads();   // hT complete + A/B bufs free before next layer
}

__global__ void __launch_bounds__(NT, 2)
cin_main(const float* __restrict__ x,
         const float* __restrict__ b0g, const float* __restrict__ b1g,
         const float* __restrict__ b2g,
         float* __restrict__ out, int Btot)
{
    extern __shared__ char smem[];
    uint32_t sb = (uint32_t)__cvta_generic_to_shared(smem);
    int tid = threadIdx.x;

    float* bias = (float*)(smem + SM_BIAS);
    for (int i = tid; i < 3 * SS; i += NT)
        bias[i] = (i < SS) ? b0g[i] : (i < 2 * SS) ? b1g[i - SS] : b2g[i - 2 * SS];

    __half* xsh = (__half*)(smem + SM_XH);
    __half* hT0 = (__half*)(smem + SM_HT0);
    __half* hT  = (__half*)(smem + SM_HT);
    int bbase = blockIdx.x * NBATCH;

    for (int i = tid; i < NBATCH * F0C * DD; i += NT) {
        int bl = i / (F0C * DD), rem = i - bl * (F0C * DD);
        int n = rem >> 5, d = rem & 31;
        int b = bbase + bl;
        float v = (b < Btot) ? x[(size_t)b * (F0C * DD) + rem] : 0.f;
        __half h = __float2half(v);
        xsh[i] = h;
        hT0[(bl * DD + d) * NFP0 + n] = h;
    }
    for (int i = tid; i < NBATCH * DD; i += NT)
        hT0[i * NFP0 + F0C] = __float2half(0.f);
    for (int i = tid; i < NBATCH * DD * 4; i += NT) {
        int row = i >> 2, c = NFH + (i & 3);
        hT[row * NFP12 + c] = __float2half(0.f);
    }
    __syncthreads();

    char* sm = smem;
    run_layer<NFP0, 0>(g_wimg, T2_0, xsh, hT0, hT, bias, out, sm, sb, bbase, Btot);
    run_layer<NFP12, 1>(g_wimg + IMG0_BYTES, T2_12, xsh, hT, hT, bias, out, sm, sb, bbase, Btot);
    run_layer<NFP12, 2>(g_wimg + IMG0_BYTES + IMG12_BYTES, T2_12, xsh, hT, hT, bias, out, sm, sb, bbase, Btot);
}

extern "C" void kernel_launch(void* const* d_in, const int* in_sizes, int n_in,
                              void* d_out, int out_size)
{
    const float* x = nullptr;
    const float* W0 = nullptr;
    const float* W1 = nullptr;
    const float* W2 = nullptr;
    const float* bb[3] = {nullptr, nullptr, nullptr};
    int nb = 0;
    long xsz = 0;

    for (int i = 0; i < n_in; i++) {
        long sz = in_sizes[i];
        const float* p = (const float*)d_in[i];
        if (sz == 1521L * SS) W0 = p;
        else if (sz == 3900L * SS) { if (!W1) W1 = p; else W2 = p; }
        else if (sz == SS) { if (nb < 3) bb[nb++] = p; }
        else { x = p; xsz = sz; }
    }

    int B = (int)(xsz / (F0C * DD));

    int n0 = T16_0 * 8 * SS, n12 = T16_12 * 8 * SS;
    prep_kernel<<<(n0 + 255) / 256, 256>>>(W0, F0C, NFP0, T16_0, 0);
    prep_kernel<<<(n12 + 255) / 256, 256>>>(W1, NFH, NFP12, T16_12, 1);
    prep_kernel<<<(n12 + 255) / 256, 256>>>(W2, NFH, NFP12, T16_12, 2);

    cudaFuncSetAttribute(cin_main, cudaFuncAttributeMaxDynamicSharedMemorySize, SMEM_TOTAL);
    cin_main<<<(B + NBATCH - 1) / NBATCH, NT, SMEM_TOTAL>>>(x, bb[0], bb[1], bb[2],
                                                            (float*)d_out, B);
}

// round 15
// speedup vs baseline: 1.0454x; 1.0454x over previous
#include <cuda_runtime.h>
#include <cuda_fp16.h>
#include <cstdint>

#define F0C 39
#define DD 32
#define SS 200
#define NFH 100
#define NPAD 208

#define NFP0 40                 // padded n-run, layer 0
#define NFP12 104               // padded n-run, layers 1,2
#define T2_0 49                 // k32 tiles (Kp0=1568)
#define T2_12 127               // k32 tiles (Kp12=4064)
#define T16_0 98
#define T16_12 254

#define NBATCH 4
#define NT 256                  // 8 warps, 2 CTAs/SM

#define BBLK16 6656
#define BBLK32 13312
#define ABUF16 4096             // 128 rows x k16 x 2B
#define ABUF32 8192
#define IMG0_BYTES (T16_0 * BBLK16)
#define IMG12_BYTES (T16_12 * BBLK16)

#define SM_BIAS 0               // 2400 -> 2432
#define SM_XH   2432            // 9984 -> 12416
#define SM_HT   12416           // 26624 -> 39040 (hT0 aliases the start; x-T dead after L0 mainloop)
#define SM_LUT  39040           // 2032 -> 41088
#define SM_A    41088           // 2*8192 -> 57472
#define SM_B    57472           // 4*13312 -> 110720
#define SMEM_TOTAL 110720

__device__ __align__(16) unsigned char g_wimg[IMG0_BYTES + 2 * IMG12_BYTES];

__device__ __forceinline__ void cp_async16(uint32_t s, const void* g) {
    asm volatile("cp.async.cg.shared.global [%0], [%1], 16;\n" :: "r"(s), "l"(g) : "memory");
}
__device__ __forceinline__ void cp_commit() { asm volatile("cp.async.commit_group;\n" ::: "memory"); }
template <int N> __device__ __forceinline__ void cp_wait() {
    asm volatile("cp.async.wait_group %0;\n" :: "n"(N) : "memory");
}
__device__ __forceinline__ uint32_t cvth2(float p0, float p1) {
    uint32_t r;
    asm("cvt.rn.f16x2.f32 %0, %1, %2;" : "=r"(r) : "f"(p1), "f"(p0));
    return r;
}
__device__ __forceinline__ void ldsm4(uint32_t* r, uint32_t a) {
    asm volatile("ldmatrix.sync.aligned.m8n8.x4.shared.b16 {%0,%1,%2,%3}, [%4];"
                 : "=r"(r[0]), "=r"(r[1]), "=r"(r[2]), "=r"(r[3]) : "r"(a));
}
__device__ __forceinline__ void ldsm2(uint32_t* r, uint32_t a) {
    asm volatile("ldmatrix.sync.aligned.m8n8.x2.shared.b16 {%0,%1}, [%2];"
                 : "=r"(r[0]), "=r"(r[1]) : "r"(a));
}
#define MMA(D, A, B0, B1)                                                     \
    asm volatile("mma.sync.aligned.m16n8k16.row.col.f32.f16.f16.f32 "         \
                 "{%0,%1,%2,%3}, {%4,%5,%6,%7}, {%8,%9}, {%0,%1,%2,%3};"      \
                 : "+f"(D[0]), "+f"(D[1]), "+f"(D[2]), "+f"(D[3])             \
                 : "r"((A)[0]), "r"((A)[1]), "r"((A)[2]), "r"((A)[3]),        \
                   "r"(B0), "r"(B1))

// ---- prep: W -> padded-K tile-packed fp16 images (26 n8-tiles incl. phantom) ----
__global__ void prep_kernel(const float* __restrict__ W, int NF, int NFP,
                            int T16, int which)
{
    unsigned char* img = g_wimg +
        ((which == 0) ? 0 : (which == 1) ? IMG0_BYTES : (IMG0_BYTES + IMG12_BYTES));
    int idx = blockIdx.x * 256 + threadIdx.x;
    if (idx >= T16 * 8 * NPAD) return;
    int o = idx % NPAD;
    int r = idx / NPAD;
    int p = r & 7, t = r >> 3;
    int c0 = t * 16 + 2 * p;
    float v[2];
#pragma unroll
    for (int u = 0; u < 2; u++) {
        int c = c0 + u;
        int m = c / NFP, j = c - m * NFP;
        v[u] = (o < SS && m < F0C && j < NF) ? W[(size_t)(m * NF + j) * SS + o] : 0.f;
    }
    uint32_t hp = cvth2(v[0], v[1]);
    int nt = o >> 3, nr = o & 7, ks = p >> 2, jj = p & 3;
    size_t off = (size_t)t * BBLK16 + (nt * 2 + ks) * 128 + nr * 16 + jj * 4;
    *(uint32_t*)(img + off) = hp;
}

// ---- main ----
__device__ __forceinline__ void prefetchB(const unsigned char* img, int t, int T2,
                                          uint32_t sb, int tid)
{
    if (t < T2) {
        const unsigned char* src = img + (size_t)t * BBLK32;
        uint32_t dst = sb + SM_B + (uint32_t)(t & 3) * (uint32_t)BBLK32;
        for (int i = tid; i < BBLK32 / 16; i += NT)
            cp_async16(dst + 16u * (uint32_t)i, src + 16 * i);
    }
    cp_commit();
}

// Pair-local A staging: 64 threads of pair mq stage batch mq's 32 rows x k32.
// Thread p = tid&63: row rloc = p&31, k16-subtile sA = p>>5, 2 octets.
template <int NFP>
__device__ __forceinline__ void stageA(int t, const uint32_t* lut,
                                       const __half* xrow, const __half* hrow,
                                       char* abuf, uint32_t arow, int sA)
{
    uint32_t base = (uint32_t)(sA * ABUF16) + arow;
#pragma unroll
    for (int kh = 0; kh < 2; kh++) {
        uint32_t L = lut[t * 4 + sA * 2 + kh];
        uint4 hv = *(const uint4*)(hrow + (L & 0xffffu));
        __half2 xx = __half2half2(xrow[L >> 16]);
        const __half2* h2 = (const __half2*)&hv;
        uint4 ov;
        ((__half2*)&ov)[0] = __hmul2(xx, h2[0]);
        ((__half2*)&ov)[1] = __hmul2(xx, h2[1]);
        ((__half2*)&ov)[2] = __hmul2(xx, h2[2]);
        ((__half2*)&ov)[3] = __hmul2(xx, h2[3]);
        *(uint4*)(abuf + base + (uint32_t)kh * 128u) = ov;
    }
}

template <int NFP, int LMODE>
__device__ void run_layer(const unsigned char* img, int T2,
                          const __half* xsh, const __half* hsrc, __half* hT,
                          const float* bias, float* out,
                          char* smem, uint32_t sb, int bbase, int Btot)
{
    const int tid = threadIdx.x;
    const int w = tid >> 5, lane = tid & 31;
    const int mq = w >> 1, nh = w & 1;       // mq 0..3 (batch), nh 0..1

    // pair-local producer mapping (warps 2mq, 2mq+1 stage batch mq)
    const int p = tid & 63;
    const int rloc = p & 31, sA = p >> 5;
    const __half* xrow = xsh + mq * (F0C * DD) + rloc;
    const __half* hrow = hsrc + (mq * DD + rloc) * NFP;
    const uint32_t arow = (uint32_t)((4 * mq + (rloc >> 3)) * 256 + (rloc & 7) * 16);

    // octet LUT (clamped past valid range; W image zero there)
    uint32_t* lut = (uint32_t*)(smem + SM_LUT);
    for (int o8 = tid; o8 < T2 * 4; o8 += NT) {
        int c0 = o8 * 8;
        int m = c0 / NFP, j0 = c0 - m * NFP;
        if (m >= F0C) { m = 0; j0 = 0; }
        lut[o8] = ((uint32_t)(m * DD) << 16) | (uint32_t)j0;
    }

    float acc[2][13][4];
#pragma unroll
    for (int mt = 0; mt < 2; mt++)
#pragma unroll
        for (int nt = 0; nt < 13; nt++)
#pragma unroll
            for (int q = 0; q < 4; q++) acc[mt][nt][q] = 0.f;

    prefetchB(img, 0, T2, sb, tid);
    prefetchB(img, 1, T2, sb, tid);
    __syncthreads();                    // lut + hsrc visible
    stageA<NFP>(0, lut, xrow, hrow, smem + SM_A, arow, sA);

    const uint32_t aoff = ((lane >> 3) & 1) * 256u + (lane >> 4) * 128u + (lane & 7) * 16u;
    const uint32_t boff = (uint32_t)lane * 16u;
    const uint32_t boff2 = (uint32_t)(lane & 15) * 16u;

    for (int t = 0; t < T2; t++) {
        if ((t & 1) == 0) __syncthreads();   // B ring: reads <= t-1 complete; also publishes stageA(0)

        if (t + 1 < T2)
            stageA<NFP>(t + 1, lut, xrow, hrow,
                        smem + SM_A + ((t + 1) & 1) * ABUF32, arow, sA);
        prefetchB(img, t + 2, T2, sb, tid);   // slot (t+2)&3, last read at t-2: safe
        cp_wait<2>();      // block t landed; t+1, t+2 in flight

        uint32_t ab = sb + SM_A + (uint32_t)(t & 1) * ABUF32 + (uint32_t)mq * 1024u;
        uint32_t bbase2 = sb + SM_B + (uint32_t)(t & 3) * (uint32_t)BBLK32 + (uint32_t)nh * 3328u;
#pragma unroll
        for (int s = 0; s < 2; s++) {
            uint32_t ah[2][4];
            ldsm4(ah[0], ab + (uint32_t)s * (uint32_t)ABUF16 + aoff);
            ldsm4(ah[1], ab + (uint32_t)s * (uint32_t)ABUF16 + 512u + aoff);
            uint32_t bb = bbase2 + (uint32_t)s * (uint32_t)BBLK16;
#pragma unroll
            for (int i = 0; i < 6; i++) {
                uint32_t bh[4];
                ldsm4(bh, bb + i * 512u + boff);
                MMA(acc[0][2 * i], ah[0], bh[0], bh[1]);
                MMA(acc[1][2 * i], ah[1], bh[0], bh[1]);
                MMA(acc[0][2 * i + 1], ah[0], bh[2], bh[3]);
                MMA(acc[1][2 * i + 1], ah[1], bh[2], bh[3]);
            }
            uint32_t bh2[2];
            ldsm2(bh2, bb + 3072u + boff2);
            MMA(acc[0][12], ah[0], bh2[0], bh2[1]);
            MMA(acc[1][12], ah[1], bh2[0], bh2[1]);
        }
        // pair barrier: A(t) reads complete in both warps; A(t+1) published
        asm volatile("bar.sync %0, 64;" :: "r"(mq + 1) : "memory");
    }
    cp_wait<0>();
    __syncthreads();   // cross-pair: all stageA hT reads done before epilogue hT writes

    // ---- epilogue: warp (mq,nh) owns batch mq fully in d ----
    int b = bbase + mq;
    bool bok = b < Btot;
    int quad = lane & 3, ldq = lane >> 2;
    const float* bi = bias + LMODE * SS;
    float* outp = out + (size_t)b * (2 * SS);
    __half* hTw = hT + (size_t)(mq * DD) * NFP12;
#pragma unroll
    for (int nt = 0; nt < 13; nt++) {
        int oe = nh * 104 + nt * 8 + 2 * quad;
        float be = bi[oe], bo = bi[oe + 1];
        float se = 0.f, so = 0.f;
#pragma unroll
        for (int mt = 0; mt < 2; mt++) {
            float v0 = fmaxf(acc[mt][nt][0] + be, 0.f);
            float v1 = fmaxf(acc[mt][nt][1] + bo, 0.f);
            float v2 = fmaxf(acc[mt][nt][2] + be, 0.f);
            float v3 = fmaxf(acc[mt][nt][3] + bo, 0.f);
            if (LMODE < 2 && bok) {
                int d0 = mt * 16 + ldq;
                if (oe < NFH) {
                    hTw[d0 * NFP12 + oe] = __float2half(v0);
                    hTw[(d0 + 8) * NFP12 + oe] = __float2half(v2);
                }
                if (oe + 1 < NFH) {
                    hTw[d0 * NFP12 + oe + 1] = __float2half(v1);
                    hTw[(d0 + 8) * NFP12 + oe + 1] = __float2half(v3);
                }
            }
            se += v0 + v2;
            so += v1 + v3;
        }
        se += __shfl_xor_sync(0xffffffffu, se, 4);
        se += __shfl_xor_sync(0xffffffffu, se, 8);
        se += __shfl_xor_sync(0xffffffffu, se, 16);
        so += __shfl_xor_sync(0xffffffffu, so, 4);
        so += __shfl_xor_sync(0xffffffffu, so, 8);
        so += __shfl_xor_sync(0xffffffffu, so, 16);
        if (ldq == 0 && bok) {
            bool de = (LMODE == 2) ? (oe < SS) : (oe >= NFH && oe < SS);
            bool dd = (LMODE == 2) ? (oe + 1 < SS) : (oe + 1 >= NFH && oe + 1 < SS);
            int che = (LMODE == 0) ? (oe - NFH) : (LMODE == 1) ? oe : (SS + oe);
            if (de) outp[che] = se;
            if (dd) outp[che + 1] = so;
        }
    }
    // zero hT pad cols 100..103 for next layer (nh=1 warps, one 8B store per d-row)
    if (LMODE < 2 && nh == 1)
        *(uint2*)((char*)hTw + lane * (NFP12 * 2) + 2 * NFH) = make_uint2(0u, 0u);
    __syncthreads();   // hT complete + A/B bufs free before next layer
}

__global__ void __launch_bounds__(NT, 2)
cin_main(const float* __restrict__ x,
         const float* __restrict__ b0g, const float* __restrict__ b1g,
         const float* __restrict__ b2g,
         float* __restrict__ out, int Btot)
{
    extern __shared__ char smem[];
    uint32_t sb = (uint32_t)__cvta_generic_to_shared(smem);
    int tid = threadIdx.x;

    float* bias = (float*)(smem + SM_BIAS);
    for (int i = tid; i < 3 * SS; i += NT)
        bias[i] = (i < SS) ? b0g[i] : (i < 2 * SS) ? b1g[i - SS] : b2g[i - 2 * SS];

    __half* xsh = (__half*)(smem + SM_XH);
    __half* hT0 = (__half*)(smem + SM_HT);   // aliases hT; dead after layer-0 mainloop
    __half* hT  = (__half*)(smem + SM_HT);
    int bbase = blockIdx.x * NBATCH;

    for (int i = tid; i < NBATCH * F0C * DD; i += NT) {
        int bl = i / (F0C * DD), rem = i - bl * (F0C * DD);
        int n = rem >> 5, d = rem & 31;
        int b = bbase + bl;
        float v = (b < Btot) ? x[(size_t)b * (F0C * DD) + rem] : 0.f;
        __half h = __float2half(v);
        xsh[i] = h;
        hT0[(bl * DD + d) * NFP0 + n] = h;
    }
    for (int i = tid; i < NBATCH * DD; i += NT)
        hT0[i * NFP0 + F0C] = __float2half(0.f);   // pad col 39
    __syncthreads();

    char* sm = smem;
    run_layer<NFP0, 0>(g_wimg, T2_0, xsh, hT0, hT, bias, out, sm, sb, bbase, Btot);
    run_layer<NFP12, 1>(g_wimg + IMG0_BYTES, T2_12, xsh, hT, hT, bias, out, sm, sb, bbase, Btot);
    run_layer<NFP12, 2>(g_wimg + IMG0_BYTES + IMG12_BYTES, T2_12, xsh, hT, hT, bias, out, sm, sb, bbase, Btot);
}

extern "C" void kernel_launch(void* const* d_in, const int* in_sizes, int n_in,
                              void* d_out, int out_size)
{
    const float* x = nullptr;
    const float* W0 = nullptr;
    const float* W1 = nullptr;
    const float* W2 = nullptr;
    const float* bb[3] = {nullptr, nullptr, nullptr};
    int nb = 0;
    long xsz = 0;

    for (int i = 0; i < n_in; i++) {
        long sz = in_sizes[i];
        const float* p = (const float*)d_in[i];
        if (sz == 1521L * SS) W0 = p;
        else if (sz == 3900L * SS) { if (!W1) W1 = p; else W2 = p; }
        else if (sz == SS) { if (nb < 3) bb[nb++] = p; }
        else { x = p; xsz = sz; }
    }

    int B = (int)(xsz / (F0C * DD));

    int n0 = T16_0 * 8 * NPAD, n12 = T16_12 * 8 * NPAD;
    prep_kernel<<<(n0 + 255) / 256, 256>>>(W0, F0C, NFP0, T16_0, 0);
    prep_kernel<<<(n12 + 255) / 256, 256>>>(W1, NFH, NFP12, T16_12, 1);
    prep_kernel<<<(n12 + 255) / 256, 256>>>(W2, NFH, NFP12, T16_12, 2);

    cudaFuncSetAttribute(cin_main, cudaFuncAttributeMaxDynamicSharedMemorySize, SMEM_TOTAL);
    cin_main<<<(B + NBATCH - 1) / NBATCH, NT, SMEM_TOTAL>>>(x, bb[0], bb[1], bb[2],
                                                            (float*)d_out, B);
}